// round 1
// baseline (speedup 1.0000x reference)
#include <cuda_runtime.h>
#include <cstdint>

#define T_STEPS 512
#define HID 32

// Scratch (allocation-free rule: __device__ globals)
__device__ float4 g_proj2[4096 * 32];   // [bucket][lane] = (P[l],P[32+l],P[64+l],P[96+l])
__device__ float4 g_Rpack[32 * 32];     // [j][lane]     = (R[j][l],R[j][32+l],R[j][64+l],R[j][96+l])

// ---------- packed f32x2 helpers ----------
__device__ __forceinline__ unsigned long long pk2(float lo, float hi) {
    unsigned long long r;
    asm("mov.b64 %0, {%1, %2};" : "=l"(r) : "f"(lo), "f"(hi));
    return r;
}
__device__ __forceinline__ void unpk2(unsigned long long v, float& lo, float& hi) {
    asm("mov.b64 {%0, %1}, %2;" : "=f"(lo), "=f"(hi) : "l"(v));
}
__device__ __forceinline__ void fma2(unsigned long long& acc, unsigned long long a, unsigned long long b) {
    asm("fma.rn.f32x2 %0, %1, %2, %0;" : "+l"(acc) : "l"(a), "l"(b));
}

// ---------- fast-but-accurate activations (EX2/RCP, ~1e-7 rel err) ----------
__device__ __forceinline__ float fex2(float x) { float y; asm("ex2.approx.f32 %0, %1;" : "=f"(y) : "f"(x)); return y; }
__device__ __forceinline__ float frcp(float x) { float y; asm("rcp.approx.f32 %0, %1;" : "=f"(y) : "f"(x)); return y; }
__device__ __forceinline__ float sigf(float x) {
    // 1/(1+2^(-x*log2e))
    return frcp(1.0f + fex2(-1.4426950408889634f * x));
}
__device__ __forceinline__ float tanhf_fast(float x) {
    // 1 - 2/(e^{2x}+1), e^{2x} = 2^{x*2log2e}
    return 1.0f - 2.0f * frcp(1.0f + fex2(2.8853900817779268f * x));
}

// ---------- prep: pack rec_kernel ----------
__global__ void prep_rpack(const float* __restrict__ R) {
    int idx = blockIdx.x * blockDim.x + threadIdx.x;
    if (idx < 32 * 32) {
        int j = idx >> 5, l = idx & 31;
        g_Rpack[idx] = make_float4(R[j * 128 + l], R[j * 128 + 32 + l],
                                   R[j * 128 + 64 + l], R[j * 128 + 96 + l]);
    }
}

// ---------- prep: per-bucket input projection  proj = emb @ kernel ----------
__global__ void prep_proj(const float* __restrict__ emb, const float* __restrict__ K, int nbuckets) {
    int idx = blockIdx.x * blockDim.x + threadIdx.x;
    int id = idx >> 5, l = idx & 31;
    if (id >= nbuckets) return;
    float a = 0.f, b = 0.f, c = 0.f, d = 0.f;
#pragma unroll
    for (int e = 0; e < 16; e++) {
        float xv = emb[id * 16 + e];
        const float* kr = K + e * 128 + l;
        a = fmaf(xv, kr[0], a);
        b = fmaf(xv, kr[32], b);
        c = fmaf(xv, kr[64], c);
        d = fmaf(xv, kr[96], d);
    }
    g_proj2[idx] = make_float4(a, b, c, d);
}

// ---------- main: warp-per-batch LSTM scan + fused head ----------
__global__ __launch_bounds__(128, 3) void lstm_main(
    const int* __restrict__ ids,
    const float* __restrict__ w1, const float* __restrict__ b1,
    const float* __restrict__ w2, const float* __restrict__ b2,
    float* __restrict__ out, int B)
{
    __shared__ __align__(16) float hb[4][2][64];   // per-warp double-buffered (h,h) pairs
    const int w = threadIdx.x >> 5;
    const int lane = threadIdx.x & 31;
    const int b = blockIdx.x * 4 + w;
    if (b >= B) return;   // uniform per warp; no block-level syncs in this kernel

    // recurrent weights: 32 j-rows x 4 owned columns, packed as 2x f32x2 per j
    unsigned long long RA[32], RB[32];
#pragma unroll
    for (int j = 0; j < 32; j++) {
        float4 r = g_Rpack[j * 32 + lane];
        RA[j] = pk2(r.x, r.y);
        RB[j] = pk2(r.z, r.w);
    }

    const int* idrow = ids + b * T_STEPS;
    int idreg = idrow[lane];                              // ids for steps 0..31
    int id0 = __shfl_sync(0xffffffffu, idreg, 0);
    float4 p = g_proj2[id0 * 32 + lane];                  // proj for step 0

    *(float2*)&hb[w][0][2 * lane] = make_float2(0.f, 0.f);  // h_0 = 0
    __syncwarp();

    float c = 0.f;
    for (int t = 0; t < T_STEPS; t++) {
        // prefetch proj for step t+1 (hidden behind this step's math)
        int tn = t + 1;
        if (((tn & 31) == 0) && (tn < T_STEPS)) idreg = idrow[tn + lane];
        int idn = __shfl_sync(0xffffffffu, idreg, tn & 31);
        float4 pn = g_proj2[idn * 32 + lane];

        unsigned long long accA = pk2(p.x, p.y);   // (z_i, z_f)
        unsigned long long accB = pk2(p.z, p.w);   // (z_c, z_o)

        const ulonglong2* hp = (const ulonglong2*)&hb[w][t & 1][0];
#pragma unroll
        for (int k = 0; k < 16; k++) {
            ulonglong2 hv = hp[k];          // ((h2k,h2k),(h2k+1,h2k+1)) broadcast LDS.128
            fma2(accA, RA[2 * k], hv.x);
            fma2(accB, RB[2 * k], hv.x);
            fma2(accA, RA[2 * k + 1], hv.y);
            fma2(accB, RB[2 * k + 1], hv.y);
        }

        float zi, zf, zc, zo;
        unpk2(accA, zi, zf);
        unpk2(accB, zc, zo);
        float ig = sigf(zi);
        float fg = sigf(zf);
        float og = sigf(zo);
        float gg = tanhf_fast(zc);
        c = fmaf(fg, c, ig * gg);
        float h = og * tanhf_fast(c);

        *(float2*)&hb[w][tn & 1][2 * lane] = make_float2(h, h);
        __syncwarp();
        p = pn;
    }

    // head: y = relu(h @ w1 + b1) @ w2 + b2  (h lives in hb[w][0])
    float s = b1[lane];
#pragma unroll
    for (int l = 0; l < HID; l++)
        s = fmaf(hb[w][0][2 * l], w1[l * 32 + lane], s);
    float r = fmaxf(s, 0.f) * w2[lane];
#pragma unroll
    for (int off = 16; off; off >>= 1)
        r += __shfl_xor_sync(0xffffffffu, r, off);
    if (lane == 0) out[b] = r + b2[0];
}

extern "C" void kernel_launch(void* const* d_in, const int* in_sizes, int n_in,
                              void* d_out, int out_size)
{
    const int*   ids  = (const int*)d_in[0];
    const float* emb  = (const float*)d_in[1];
    const float* kern = (const float*)d_in[2];
    const float* rec  = (const float*)d_in[3];
    const float* w1   = (const float*)d_in[4];
    const float* b1   = (const float*)d_in[5];
    const float* w2   = (const float*)d_in[6];
    const float* b2   = (const float*)d_in[7];

    int B = in_sizes[0] / T_STEPS;
    int nbuckets = in_sizes[1] / 16;
    if (nbuckets > 4096) nbuckets = 4096;

    prep_rpack<<<8, 128>>>(rec);
    prep_proj<<<(nbuckets * 32 + 127) / 128, 128>>>(emb, kern, nbuckets);
    lstm_main<<<(B + 3) / 4, 128>>>(ids, w1, b1, w2, b2, (float*)d_out, B);
}